// round 15
// baseline (speedup 1.0000x reference)
#include <cuda_runtime.h>
#include <cuda_fp16.h>
#include <cstdint>

#define NQ     128
#define NK     2048
#define D5     768
#define SEQ    32
#define ZD     24
#define NTHR   256
#define KCHUNK 32

// smem: ks0 = 32 kk * 1024B (u64 frags, swizzled), ks1 = 32 kk * 512B (u32 frags)
#define SB1_OFF 32768
#define SMEM_BYTES (32768 + 16384)

#define SWZ(x) ((x) ^ (((x) >> 3) & 0x70))

typedef unsigned long long ull;

__device__ __forceinline__ uint32_t pkh(float lo, float hi) {
    __half2 h = __floats2half2_rn(lo, hi);
    return *reinterpret_cast<uint32_t*>(&h);
}
__device__ __forceinline__ uint32_t hmax2u(uint32_t a, uint32_t b) {
    uint32_t d; asm("max.f16x2 %0, %1, %2;" : "=r"(d) : "r"(a), "r"(b));
    return d;
}
__device__ __forceinline__ uint32_t hadd2u(uint32_t a, uint32_t b) {
    uint32_t d; asm("add.f16x2 %0, %1, %2;" : "=r"(d) : "r"(a), "r"(b));
    return d;
}
__device__ __forceinline__ uint32_t hfma2u(uint32_t a, uint32_t b, uint32_t c) {
    uint32_t d; asm("fma.rn.f16x2 %0, %1, %2, %3;" : "=r"(d) : "r"(a), "r"(b), "r"(c));
    return d;
}
__device__ __forceinline__ uint32_t prmtu(uint32_t a, uint32_t b, uint32_t sel) {
    uint32_t d; asm("prmt.b32 %0, %1, %2, %3;" : "=r"(d) : "r"(a), "r"(b), "r"(sel));
    return d;
}
__device__ __forceinline__ float2 h2f2(uint32_t p) {
    __half2 h = *reinterpret_cast<__half2*>(&p);
    return __half22float2(h);
}

__device__ __forceinline__ void hmma_z(uint32_t* c, const uint32_t* a, ull b) {
    uint32_t b0 = (uint32_t)b, b1 = (uint32_t)(b >> 32);
    asm volatile(
        "mma.sync.aligned.m16n8k16.row.col.f16.f16.f16.f16 "
        "{%0,%1}, {%2,%3,%4,%5}, {%6,%7}, {%8,%8};"
        : "=r"(c[0]), "=r"(c[1])
        : "r"(a[0]), "r"(a[1]), "r"(a[2]), "r"(a[3]), "r"(b0), "r"(b1), "r"(0u));
}
__device__ __forceinline__ void hmma_k8(uint32_t* c, uint32_t a0, uint32_t a1,
                                        uint32_t b0) {
    asm volatile(
        "mma.sync.aligned.m16n8k8.row.col.f16.f16.f16.f16 "
        "{%0,%1}, {%2,%3}, {%4}, {%0,%1};"
        : "+r"(c[0]), "+r"(c[1])
        : "r"(a0), "r"(a1), "r"(b0));
}

extern __shared__ char sbuf[];

__global__ __launch_bounds__(NTHR, 4)
void matcher_hmma(const float* __restrict__ tgt,
                  const float* __restrict__ mem,
                  float* __restrict__ out)
{
    const int tid  = threadIdx.x;
    const int warp = tid >> 5;
    const int lane = tid & 31;
    const int gr   = lane >> 2;
    const int gc   = lane & 3;

    const int q0 = (blockIdx.x >> 6) * 8;       // 16 q-chunks
    const int k0 = (blockIdx.x & 63) * KCHUNK;  // 64 k-chunks
    const int q  = q0 + warp;

    // ---- Stage ALL 32 k-rows (4 tasks/thread), fragment-major layout ----
    // ks0: u64 frag (gr,gc,ni) at kk*1024 + SWZ((gc*8+gr)*32 + ni*8)
    // ks1: u32 frag (gr,gc,ni) at SB1_OFF + kk*512 + (gc*8+gr)*16 + ni*4
    #pragma unroll
    for (int i = 0; i < 4; ++i) {
        int task = tid + i * NTHR;              // 0..1023
        int kk = task >> 5, s = task & 31;
        const float4* p = reinterpret_cast<const float4*>(
            mem + (size_t)(k0 + kk) * D5 + s * ZD);
        float4 x0 = p[0], x1 = p[1], x2 = p[2], x3 = p[3], x4 = p[4], x5 = p[5];
        uint32_t p0 = pkh(x0.x, x0.y), p1 = pkh(x0.z, x0.w);
        uint32_t p2 = pkh(x1.x, x1.y), p3 = pkh(x1.z, x1.w);
        uint32_t p4 = pkh(x2.x, x2.y), p5 = pkh(x2.z, x2.w);
        uint32_t p6 = pkh(x3.x, x3.y), p7 = pkh(x3.z, x3.w);
        uint32_t p8 = pkh(x4.x, x4.y), p9 = pkh(x4.z, x4.w);
        uint32_t pA = pkh(x5.x, x5.y), pB = pkh(x5.z, x5.w);
        int grs = s & 7, nis = s >> 3;
        char* r0 = sbuf + kk * 1024;
        *reinterpret_cast<ull*>(r0 + SWZ((0 * 8 + grs) * 32 + nis * 8)) = (ull)p0 | ((ull)p4 << 32);
        *reinterpret_cast<ull*>(r0 + SWZ((1 * 8 + grs) * 32 + nis * 8)) = (ull)p1 | ((ull)p5 << 32);
        *reinterpret_cast<ull*>(r0 + SWZ((2 * 8 + grs) * 32 + nis * 8)) = (ull)p2 | ((ull)p6 << 32);
        *reinterpret_cast<ull*>(r0 + SWZ((3 * 8 + grs) * 32 + nis * 8)) = (ull)p3 | ((ull)p7 << 32);
        char* r1 = sbuf + SB1_OFF + kk * 512 + grs * 16 + nis * 4;
        *reinterpret_cast<uint32_t*>(r1 + 0)   = p8;
        *reinterpret_cast<uint32_t*>(r1 + 128) = p9;
        *reinterpret_cast<uint32_t*>(r1 + 256) = pA;
        *reinterpret_cast<uint32_t*>(r1 + 384) = pB;
    }

    // A fragments (f16 pairs): ks0 full 4 regs (k16), ks1 2 regs (k8)
    uint32_t afr0[2][4], afr1[2][2];
    {
        const float* a = tgt + (size_t)q * D5;
        #pragma unroll
        for (int mi = 0; mi < 2; ++mi) {
            int r = gr + 16 * mi;
            const float* r0 = a + r * ZD;
            const float* r1 = a + (r + 8) * ZD;
            afr0[mi][0] = pkh(r0[2 * gc],      r0[2 * gc + 1]);
            afr0[mi][1] = pkh(r1[2 * gc],      r1[2 * gc + 1]);
            afr0[mi][2] = pkh(r0[2 * gc + 8],  r0[2 * gc + 9]);
            afr0[mi][3] = pkh(r1[2 * gc + 8],  r1[2 * gc + 9]);
            afr1[mi][0] = pkh(r0[2 * gc + 16], r0[2 * gc + 17]);
            afr1[mi][1] = pkh(r1[2 * gc + 16], r1[2 * gc + 17]);
        }
    }

    float* __restrict__ out0 = out + (size_t)q * NK;
    float* __restrict__ out1 = out0 + (size_t)NQ * NK;

    __syncthreads();

    const int L = gc * 8 + gr;                       // 0..31
    const uint32_t c0 = SWZ((uint32_t)(L * 32));
    const uint32_t c1 = SWZ((uint32_t)(L * 32 + 16));
    const uint32_t cH = (uint32_t)(SB1_OFF + L * 16);

    const int p0b = (lane >> 2) & 1;   // gr bit0 (xor 4)
    const int p1b = (lane >> 3) & 1;   // gr bit1 (xor 8)
    const int q0b = lane & 1;          // gc bit0 (xor 1)
    const int q1b = (lane >> 1) & 1;   // gc bit1 (xor 2)

    // Per-pair compute: loads + MMA + pooling; returns part packed in both f16 halves
    auto do_pair = [&](int kk) -> uint32_t {
        const char* b0 = sbuf + kk * 1024;
        ulonglong2 Av = *reinterpret_cast<const ulonglong2*>(b0 + c0);   // ni 0,1
        ulonglong2 Bv = *reinterpret_cast<const ulonglong2*>(b0 + c1);   // ni 2,3
        uint4 H = *reinterpret_cast<const uint4*>(sbuf + kk * 512 + cH); // k8 frags
        ull bf[4] = { Av.x, Av.y, Bv.x, Bv.y };
        uint32_t bh[4] = { H.x, H.y, H.z, H.w };

        uint32_t acc[2][4][2];
        #pragma unroll
        for (int mi = 0; mi < 2; ++mi)
            #pragma unroll
            for (int ni = 0; ni < 4; ++ni)
                hmma_z(acc[mi][ni], afr0[mi], bf[ni]);
        #pragma unroll
        for (int mi = 0; mi < 2; ++mi)
            #pragma unroll
            for (int ni = 0; ni < 4; ++ni)
                hmma_k8(acc[mi][ni], afr1[mi][0], afr1[mi][1], bh[ni]);

        // In-thread packed row maxes over ni (4 slots)
        uint32_t rm[4];
        #pragma unroll
        for (int mi = 0; mi < 2; ++mi)
            #pragma unroll
            for (int j = 0; j < 2; ++j) {
                uint32_t m = hmax2u(acc[mi][0][j], acc[mi][1][j]);
                m = hmax2u(m, acc[mi][2][j]);
                rm[2 * mi + j] = hmax2u(m, acc[mi][3][j]);
            }
        // In-thread packed col maxes over rows (4 slots)
        uint32_t cm[4];
        #pragma unroll
        for (int ni = 0; ni < 4; ++ni) {
            uint32_t m = hmax2u(acc[0][ni][0], acc[0][ni][1]);
            m = hmax2u(m, acc[1][ni][0]);
            cm[ni] = hmax2u(m, acc[1][ni][1]);
        }

        // Rows: reduce-scatter over gc bits (xor 1, 2)
        uint32_t ro;
        {
            uint32_t s0 = q0b ? rm[0] : rm[2], k0v = q0b ? rm[2] : rm[0];
            uint32_t s1 = q0b ? rm[1] : rm[3], k1v = q0b ? rm[3] : rm[1];
            uint32_t w0 = hmax2u(k0v, __shfl_xor_sync(0xffffffffu, s0, 1));
            uint32_t w1 = hmax2u(k1v, __shfl_xor_sync(0xffffffffu, s1, 1));
            uint32_t s2 = q1b ? w0 : w1, k2v = q1b ? w1 : w0;
            ro = hmax2u(k2v, __shfl_xor_sync(0xffffffffu, s2, 2));
        }
        // Cols: reduce-scatter over gr bits (xor 4, 8) + butterfly (16)
        uint32_t cp;
        {
            uint32_t v4[2];
            #pragma unroll
            for (int j = 0; j < 2; ++j) {
                uint32_t s = p0b ? cm[j] : cm[j + 2];
                uint32_t k = p0b ? cm[j + 2] : cm[j];
                v4[j] = hmax2u(k, __shfl_xor_sync(0xffffffffu, s, 4));
            }
            uint32_t s = p1b ? v4[0] : v4[1];
            uint32_t k = p1b ? v4[1] : v4[0];
            uint32_t v2 = hmax2u(k, __shfl_xor_sync(0xffffffffu, s, 8));
            cp = hmax2u(v2, __shfl_xor_sync(0xffffffffu, v2, 16));
        }
        // Packed merges: rowm = max of halves (both halves), csum = sum of halves
        uint32_t rowm = hmax2u(ro, prmtu(ro, ro, 0x1032u));
        uint32_t csum = hadd2u(cp, prmtu(cp, cp, 0x1032u));
        // part = rowm + 0.5 * csum (both halves equal)
        return hfma2u(csum, 0x38003800u, rowm);
    };

    #pragma unroll 1
    for (int kb = 0; kb < KCHUNK; kb += 8) {
        uint32_t pp[4];
        #pragma unroll 1
        for (int j = 0; j < 4; ++j) {
            uint32_t pf0 = do_pair(kb + 2 * j);
            uint32_t pf1 = do_pair(kb + 2 * j + 1);
            pp[j] = prmtu(pf0, pf1, 0x5410u);   // (partEven, partOdd) packed
        }

        // Batched packed warp-sum: 4 u32 = 8 pair-partials, value-splitting
        uint32_t t2[2];
        {
            bool hi = (lane & 1);
            #pragma unroll
            for (int j = 0; j < 2; ++j) {
                uint32_t send = hi ? pp[j] : pp[j + 2];
                uint32_t keep = hi ? pp[j + 2] : pp[j];
                t2[j] = hadd2u(keep, __shfl_xor_sync(0xffffffffu, send, 1));
            }
        }
        uint32_t v;
        {
            bool hi = (lane & 2);
            uint32_t send = hi ? t2[0] : t2[1];
            uint32_t keep = hi ? t2[1] : t2[0];
            v = hadd2u(keep, __shfl_xor_sync(0xffffffffu, send, 2));
        }
        v = hadd2u(v, __shfl_xor_sync(0xffffffffu, v, 4));
        v = hadd2u(v, __shfl_xor_sync(0xffffffffu, v, 8));
        v = hadd2u(v, __shfl_xor_sync(0xffffffffu, v, 16));

        if (lane < 4) {
            int g = ((lane & 1) << 1) | ((lane >> 1) & 1);   // owned pp index
            float2 f = h2f2(v);
            float ra = 1.0f / (1.0f + __expf(f.x * -0.015625f));
            float rb = 1.0f / (1.0f + __expf(f.y * -0.015625f));
            int k = k0 + kb + 2 * g;
            *reinterpret_cast<float2*>(out0 + k) = make_float2(ra, rb);
            *reinterpret_cast<float2*>(out1 + k) = make_float2(ra, rb);
        }
    }
}

extern "C" void kernel_launch(void* const* d_in, const int* in_sizes, int n_in,
                              void* d_out, int out_size)
{
    const float* tgt = (const float*)d_in[0];   // [128, 768]
    const float* mem = (const float*)d_in[1];   // [2048, 768]
    float* out = (float*)d_out;                 // [2, 128, 2048]
    (void)in_sizes; (void)n_in; (void)out_size;

    cudaFuncSetAttribute(matcher_hmma,
                         cudaFuncAttributeMaxDynamicSharedMemorySize, SMEM_BYTES);
    matcher_hmma<<<1024, NTHR, SMEM_BYTES>>>(tgt, mem, out);
}

// round 16
// speedup vs baseline: 1.0611x; 1.0611x over previous
#include <cuda_runtime.h>
#include <cuda_fp16.h>
#include <cstdint>

#define NQ     128
#define NK     2048
#define D5     768
#define SEQ    32
#define ZD     24
#define NTHR   256
#define KCHUNK 32

// smem: ks0 = 32 kk * 1024B (two 512B panels), ks1 = 32 kk * 512B (one panel)
#define SB1_OFF 32768
#define SMEM_BYTES (32768 + 16384)

typedef unsigned long long ull;

__device__ __forceinline__ uint32_t pkh(float lo, float hi) {
    __half2 h = __floats2half2_rn(lo, hi);
    return *reinterpret_cast<uint32_t*>(&h);
}
__device__ __forceinline__ uint32_t hmax2u(uint32_t a, uint32_t b) {
    uint32_t d; asm("max.f16x2 %0, %1, %2;" : "=r"(d) : "r"(a), "r"(b));
    return d;
}
__device__ __forceinline__ uint32_t hadd2u(uint32_t a, uint32_t b) {
    uint32_t d; asm("add.f16x2 %0, %1, %2;" : "=r"(d) : "r"(a), "r"(b));
    return d;
}
__device__ __forceinline__ uint32_t hfma2u(uint32_t a, uint32_t b, uint32_t c) {
    uint32_t d; asm("fma.rn.f16x2 %0, %1, %2, %3;" : "=r"(d) : "r"(a), "r"(b), "r"(c));
    return d;
}
__device__ __forceinline__ uint32_t prmtu(uint32_t a, uint32_t b, uint32_t sel) {
    uint32_t d; asm("prmt.b32 %0, %1, %2, %3;" : "=r"(d) : "r"(a), "r"(b), "r"(sel));
    return d;
}
__device__ __forceinline__ float2 h2f2(uint32_t p) {
    __half2 h = *reinterpret_cast<__half2*>(&p);
    return __half22float2(h);
}

__device__ __forceinline__ void hmma_z(uint32_t* c, const uint32_t* a, ull b) {
    uint32_t b0 = (uint32_t)b, b1 = (uint32_t)(b >> 32);
    asm volatile(
        "mma.sync.aligned.m16n8k16.row.col.f16.f16.f16.f16 "
        "{%0,%1}, {%2,%3,%4,%5}, {%6,%7}, {%8,%8};"
        : "=r"(c[0]), "=r"(c[1])
        : "r"(a[0]), "r"(a[1]), "r"(a[2]), "r"(a[3]), "r"(b0), "r"(b1), "r"(0u));
}
__device__ __forceinline__ void hmma_k8(uint32_t* c, uint32_t a0, uint32_t a1,
                                        uint32_t b0) {
    asm volatile(
        "mma.sync.aligned.m16n8k8.row.col.f16.f16.f16.f16 "
        "{%0,%1}, {%2,%3}, {%4}, {%0,%1};"
        : "+r"(c[0]), "+r"(c[1])
        : "r"(a0), "r"(a1), "r"(b0));
}

extern __shared__ char sbuf[];

__global__ __launch_bounds__(NTHR, 4)
void matcher_hmma(const float* __restrict__ tgt,
                  const float* __restrict__ mem,
                  float* __restrict__ out)
{
    const int tid  = threadIdx.x;
    const int warp = tid >> 5;
    const int lane = tid & 31;
    const int gr   = lane >> 2;
    const int gc   = lane & 3;

    const int q0 = (blockIdx.x >> 6) * 8;       // 16 q-chunks
    const int k0 = (blockIdx.x & 63) * KCHUNK;  // 64 k-chunks
    const int q  = q0 + warp;

    // ---- Stage ALL 32 k-rows (4 tasks/thread), lane-major panels ----
    // Consumer lane L=(gr*4+gc): ks0 frag(ni) at kk*1024 + (ni>>1)*512 + L*16 + (ni&1)*8
    //                            ks1 frag(ni) at SB1_OFF + kk*512 + L*16 + ni*4
    // Stager task (kk,s) provides frags for gr=s&7 (k16: s=gr+8ni -> ni=s>>3),
    // and for ks1 (gr=s&7, gc=s>>3).
    #pragma unroll
    for (int i = 0; i < 4; ++i) {
        int task = tid + i * NTHR;              // 0..1023
        int kk = task >> 5, s = task & 31;
        const float4* p = reinterpret_cast<const float4*>(
            mem + (size_t)(k0 + kk) * D5 + s * ZD);
        float4 x0 = p[0], x1 = p[1], x2 = p[2], x3 = p[3], x4 = p[4], x5 = p[5];
        uint32_t p0 = pkh(x0.x, x0.y), p1 = pkh(x0.z, x0.w);
        uint32_t p2 = pkh(x1.x, x1.y), p3 = pkh(x1.z, x1.w);
        uint32_t p4 = pkh(x2.x, x2.y), p5 = pkh(x2.z, x2.w);
        uint32_t p6 = pkh(x3.x, x3.y), p7 = pkh(x3.z, x3.w);
        uint32_t p8 = pkh(x4.x, x4.y), p9 = pkh(x4.z, x4.w);
        uint32_t pA = pkh(x5.x, x5.y), pB = pkh(x5.z, x5.w);
        int grs = s & 7, nis = s >> 3;
        // ks0: 4 STS.64, one per gc=j; frag content zip_j = p_j | p_{j+4}<<32
        char* b0 = sbuf + kk * 1024 + ((nis >> 1) * 512) + ((nis & 1) * 8);
        *reinterpret_cast<ull*>(b0 + (grs * 4 + 0) * 16) = (ull)p0 | ((ull)p4 << 32);
        *reinterpret_cast<ull*>(b0 + (grs * 4 + 1) * 16) = (ull)p1 | ((ull)p5 << 32);
        *reinterpret_cast<ull*>(b0 + (grs * 4 + 2) * 16) = (ull)p2 | ((ull)p6 << 32);
        *reinterpret_cast<ull*>(b0 + (grs * 4 + 3) * 16) = (ull)p3 | ((ull)p7 << 32);
        // ks1: one STS.128 (lane L' = grs*4 + nis)
        *reinterpret_cast<uint4*>(sbuf + SB1_OFF + kk * 512 + (grs * 4 + nis) * 16) =
            make_uint4(p8, p9, pA, pB);
    }

    // A fragments (f16 pairs): ks0 full 4 regs (k16), ks1 2 regs (k8)
    uint32_t afr0[2][4], afr1[2][2];
    {
        const float* a = tgt + (size_t)q * D5;
        #pragma unroll
        for (int mi = 0; mi < 2; ++mi) {
            int r = gr + 16 * mi;
            const float* r0 = a + r * ZD;
            const float* r1 = a + (r + 8) * ZD;
            afr0[mi][0] = pkh(r0[2 * gc],      r0[2 * gc + 1]);
            afr0[mi][1] = pkh(r1[2 * gc],      r1[2 * gc + 1]);
            afr0[mi][2] = pkh(r0[2 * gc + 8],  r0[2 * gc + 9]);
            afr0[mi][3] = pkh(r1[2 * gc + 8],  r1[2 * gc + 9]);
            afr1[mi][0] = pkh(r0[2 * gc + 16], r0[2 * gc + 17]);
            afr1[mi][1] = pkh(r1[2 * gc + 16], r1[2 * gc + 17]);
        }
    }

    float* __restrict__ out0 = out + (size_t)q * NK;
    float* __restrict__ out1 = out0 + (size_t)NQ * NK;

    __syncthreads();

    const uint32_t cL = (uint32_t)(lane * 16);

    const int p0b = (lane >> 2) & 1;   // gr bit0 (xor 4)
    const int p1b = (lane >> 3) & 1;   // gr bit1 (xor 8)
    const int q0b = lane & 1;          // gc bit0 (xor 1)
    const int q1b = (lane >> 1) & 1;   // gc bit1 (xor 2)

    auto do_pair = [&](int kk) -> uint32_t {
        const char* b0 = sbuf + kk * 1024;
        ulonglong2 Av = *reinterpret_cast<const ulonglong2*>(b0 + cL);         // ni 0,1
        ulonglong2 Bv = *reinterpret_cast<const ulonglong2*>(b0 + 512 + cL);   // ni 2,3
        uint4 H = *reinterpret_cast<const uint4*>(sbuf + SB1_OFF + kk * 512 + cL);
        ull bf[4] = { Av.x, Av.y, Bv.x, Bv.y };
        uint32_t bh[4] = { H.x, H.y, H.z, H.w };

        uint32_t acc[2][4][2];
        #pragma unroll
        for (int mi = 0; mi < 2; ++mi)
            #pragma unroll
            for (int ni = 0; ni < 4; ++ni)
                hmma_z(acc[mi][ni], afr0[mi], bf[ni]);
        #pragma unroll
        for (int mi = 0; mi < 2; ++mi)
            #pragma unroll
            for (int ni = 0; ni < 4; ++ni)
                hmma_k8(acc[mi][ni], afr1[mi][0], afr1[mi][1], bh[ni]);

        // In-thread packed row maxes over ni (4 slots)
        uint32_t rm[4];
        #pragma unroll
        for (int mi = 0; mi < 2; ++mi)
            #pragma unroll
            for (int j = 0; j < 2; ++j) {
                uint32_t m = hmax2u(acc[mi][0][j], acc[mi][1][j]);
                m = hmax2u(m, acc[mi][2][j]);
                rm[2 * mi + j] = hmax2u(m, acc[mi][3][j]);
            }
        // In-thread packed col maxes over rows (4 slots)
        uint32_t cm[4];
        #pragma unroll
        for (int ni = 0; ni < 4; ++ni) {
            uint32_t m = hmax2u(acc[0][ni][0], acc[0][ni][1]);
            m = hmax2u(m, acc[1][ni][0]);
            cm[ni] = hmax2u(m, acc[1][ni][1]);
        }

        // Rows: reduce-scatter over gc bits (xor 1, 2)
        uint32_t ro;
        {
            uint32_t s0 = q0b ? rm[0] : rm[2], k0v = q0b ? rm[2] : rm[0];
            uint32_t s1 = q0b ? rm[1] : rm[3], k1v = q0b ? rm[3] : rm[1];
            uint32_t w0 = hmax2u(k0v, __shfl_xor_sync(0xffffffffu, s0, 1));
            uint32_t w1 = hmax2u(k1v, __shfl_xor_sync(0xffffffffu, s1, 1));
            uint32_t s2 = q1b ? w0 : w1, k2v = q1b ? w1 : w0;
            ro = hmax2u(k2v, __shfl_xor_sync(0xffffffffu, s2, 2));
        }
        // Cols: reduce-scatter over gr bits (xor 4, 8) + butterfly (16)
        uint32_t cp;
        {
            uint32_t v4[2];
            #pragma unroll
            for (int j = 0; j < 2; ++j) {
                uint32_t s = p0b ? cm[j] : cm[j + 2];
                uint32_t k = p0b ? cm[j + 2] : cm[j];
                v4[j] = hmax2u(k, __shfl_xor_sync(0xffffffffu, s, 4));
            }
            uint32_t s = p1b ? v4[0] : v4[1];
            uint32_t k = p1b ? v4[1] : v4[0];
            uint32_t v2 = hmax2u(k, __shfl_xor_sync(0xffffffffu, s, 8));
            cp = hmax2u(v2, __shfl_xor_sync(0xffffffffu, v2, 16));
        }
        // Packed merges: rowm = max of halves, csum = sum of halves
        uint32_t rowm = hmax2u(ro, prmtu(ro, ro, 0x1032u));
        uint32_t csum = hadd2u(cp, prmtu(cp, cp, 0x1032u));
        return hfma2u(csum, 0x38003800u, rowm);   // part = rowm + 0.5*csum
    };

    #pragma unroll 1
    for (int kb = 0; kb < KCHUNK; kb += 8) {
        uint32_t pp[4];
        #pragma unroll 1
        for (int j = 0; j < 4; ++j) {
            uint32_t pf0 = do_pair(kb + 2 * j);
            uint32_t pf1 = do_pair(kb + 2 * j + 1);
            pp[j] = prmtu(pf0, pf1, 0x5410u);   // (partEven, partOdd) packed
        }

        // Batched packed warp-sum: 4 u32 = 8 pair-partials, value-splitting
        uint32_t t2[2];
        {
            bool hi = (lane & 1);
            #pragma unroll
            for (int j = 0; j < 2; ++j) {
                uint32_t send = hi ? pp[j] : pp[j + 2];
                uint32_t keep = hi ? pp[j + 2] : pp[j];
                t2[j] = hadd2u(keep, __shfl_xor_sync(0xffffffffu, send, 1));
            }
        }
        uint32_t v;
        {
            bool hi = (lane & 2);
            uint32_t send = hi ? t2[0] : t2[1];
            uint32_t keep = hi ? t2[1] : t2[0];
            v = hadd2u(keep, __shfl_xor_sync(0xffffffffu, send, 2));
        }
        v = hadd2u(v, __shfl_xor_sync(0xffffffffu, v, 4));
        v = hadd2u(v, __shfl_xor_sync(0xffffffffu, v, 8));
        v = hadd2u(v, __shfl_xor_sync(0xffffffffu, v, 16));

        if (lane < 4) {
            int g = ((lane & 1) << 1) | ((lane >> 1) & 1);   // owned pp index
            float2 f = h2f2(v);
            float ra = 1.0f / (1.0f + __expf(f.x * -0.015625f));
            float rb = 1.0f / (1.0f + __expf(f.y * -0.015625f));
            int k = k0 + kb + 2 * g;
            *reinterpret_cast<float2*>(out0 + k) = make_float2(ra, rb);
            *reinterpret_cast<float2*>(out1 + k) = make_float2(ra, rb);
        }
    }
}

extern "C" void kernel_launch(void* const* d_in, const int* in_sizes, int n_in,
                              void* d_out, int out_size)
{
    const float* tgt = (const float*)d_in[0];   // [128, 768]
    const float* mem = (const float*)d_in[1];   // [2048, 768]
    float* out = (float*)d_out;                 // [2, 128, 2048]
    (void)in_sizes; (void)n_in; (void)out_size;

    cudaFuncSetAttribute(matcher_hmma,
                         cudaFuncAttributeMaxDynamicSharedMemorySize, SMEM_BYTES);
    matcher_hmma<<<1024, NTHR, SMEM_BYTES>>>(tgt, mem, out);
}

// round 17
// speedup vs baseline: 1.0733x; 1.0115x over previous
#include <cuda_runtime.h>
#include <cuda_fp16.h>
#include <cstdint>

#define NQ     128
#define NK     2048
#define D5     768
#define SEQ    32
#define ZD     24
#define NTHR   256
#define KCHUNK 16

// smem: ks0 = 16 kk * 1024B (two 512B panels), ks1 = 16 kk * 512B
#define SB1_OFF 16384
#define SMEM_BYTES (16384 + 8192)

typedef unsigned long long ull;

__device__ __forceinline__ uint32_t pkh(float lo, float hi) {
    __half2 h = __floats2half2_rn(lo, hi);
    return *reinterpret_cast<uint32_t*>(&h);
}
__device__ __forceinline__ uint32_t hmax2u(uint32_t a, uint32_t b) {
    uint32_t d; asm("max.f16x2 %0, %1, %2;" : "=r"(d) : "r"(a), "r"(b));
    return d;
}
__device__ __forceinline__ uint32_t hadd2u(uint32_t a, uint32_t b) {
    uint32_t d; asm("add.f16x2 %0, %1, %2;" : "=r"(d) : "r"(a), "r"(b));
    return d;
}
__device__ __forceinline__ uint32_t hfma2u(uint32_t a, uint32_t b, uint32_t c) {
    uint32_t d; asm("fma.rn.f16x2 %0, %1, %2, %3;" : "=r"(d) : "r"(a), "r"(b), "r"(c));
    return d;
}
__device__ __forceinline__ uint32_t prmtu(uint32_t a, uint32_t b, uint32_t sel) {
    uint32_t d; asm("prmt.b32 %0, %1, %2, %3;" : "=r"(d) : "r"(a), "r"(b), "r"(sel));
    return d;
}
__device__ __forceinline__ float2 h2f2(uint32_t p) {
    __half2 h = *reinterpret_cast<__half2*>(&p);
    return __half22float2(h);
}

__device__ __forceinline__ void hmma_z(uint32_t* c, const uint32_t* a, ull b) {
    uint32_t b0 = (uint32_t)b, b1 = (uint32_t)(b >> 32);
    asm volatile(
        "mma.sync.aligned.m16n8k16.row.col.f16.f16.f16.f16 "
        "{%0,%1}, {%2,%3,%4,%5}, {%6,%7}, {%8,%8};"
        : "=r"(c[0]), "=r"(c[1])
        : "r"(a[0]), "r"(a[1]), "r"(a[2]), "r"(a[3]), "r"(b0), "r"(b1), "r"(0u));
}
__device__ __forceinline__ void hmma_k8(uint32_t* c, uint32_t a0, uint32_t a1,
                                        uint32_t b0) {
    asm volatile(
        "mma.sync.aligned.m16n8k8.row.col.f16.f16.f16.f16 "
        "{%0,%1}, {%2,%3}, {%4}, {%0,%1};"
        : "+r"(c[0]), "+r"(c[1])
        : "r"(a0), "r"(a1), "r"(b0));
}

extern __shared__ char sbuf[];

__global__ __launch_bounds__(NTHR, 3)
void matcher_hmma(const float* __restrict__ tgt,
                  const float* __restrict__ mem,
                  float* __restrict__ out)
{
    const int tid  = threadIdx.x;
    const int warp = tid >> 5;
    const int lane = tid & 31;
    const int gr   = lane >> 2;
    const int gc   = lane & 3;

    const int q0 = (blockIdx.x >> 7) * 16;       // 8 q-chunks of 16
    const int k0 = (blockIdx.x & 127) * KCHUNK;  // 128 k-chunks of 16

    // ---- Stage 16 k-rows (2 tasks/thread), lane-major panels (R16 layout) ----
    #pragma unroll
    for (int i = 0; i < 2; ++i) {
        int task = tid + i * NTHR;              // 0..511
        int kk = task >> 5, s = task & 31;
        const float4* p = reinterpret_cast<const float4*>(
            mem + (size_t)(k0 + kk) * D5 + s * ZD);
        float4 x0 = p[0], x1 = p[1], x2 = p[2], x3 = p[3], x4 = p[4], x5 = p[5];
        uint32_t p0 = pkh(x0.x, x0.y), p1 = pkh(x0.z, x0.w);
        uint32_t p2 = pkh(x1.x, x1.y), p3 = pkh(x1.z, x1.w);
        uint32_t p4 = pkh(x2.x, x2.y), p5 = pkh(x2.z, x2.w);
        uint32_t p6 = pkh(x3.x, x3.y), p7 = pkh(x3.z, x3.w);
        uint32_t p8 = pkh(x4.x, x4.y), p9 = pkh(x4.z, x4.w);
        uint32_t pA = pkh(x5.x, x5.y), pB = pkh(x5.z, x5.w);
        int grs = s & 7, nis = s >> 3;
        char* b0 = sbuf + kk * 1024 + ((nis >> 1) * 512) + ((nis & 1) * 8);
        *reinterpret_cast<ull*>(b0 + (grs * 4 + 0) * 16) = (ull)p0 | ((ull)p4 << 32);
        *reinterpret_cast<ull*>(b0 + (grs * 4 + 1) * 16) = (ull)p1 | ((ull)p5 << 32);
        *reinterpret_cast<ull*>(b0 + (grs * 4 + 2) * 16) = (ull)p2 | ((ull)p6 << 32);
        *reinterpret_cast<ull*>(b0 + (grs * 4 + 3) * 16) = (ull)p3 | ((ull)p7 << 32);
        *reinterpret_cast<uint4*>(sbuf + SB1_OFF + kk * 512 + (grs * 4 + nis) * 16) =
            make_uint4(p8, p9, pA, pB);
    }

    // A fragments for TWO q rows per warp: q = q0 + 2*warp + qi
    uint32_t afr0[2][2][4], afr1[2][2][2];
    #pragma unroll
    for (int qi = 0; qi < 2; ++qi) {
        const float* a = tgt + (size_t)(q0 + 2 * warp + qi) * D5;
        #pragma unroll
        for (int mi = 0; mi < 2; ++mi) {
            int r = gr + 16 * mi;
            const float* r0 = a + r * ZD;
            const float* r1 = a + (r + 8) * ZD;
            afr0[qi][mi][0] = pkh(r0[2 * gc],      r0[2 * gc + 1]);
            afr0[qi][mi][1] = pkh(r1[2 * gc],      r1[2 * gc + 1]);
            afr0[qi][mi][2] = pkh(r0[2 * gc + 8],  r0[2 * gc + 9]);
            afr0[qi][mi][3] = pkh(r1[2 * gc + 8],  r1[2 * gc + 9]);
            afr1[qi][mi][0] = pkh(r0[2 * gc + 16], r0[2 * gc + 17]);
            afr1[qi][mi][1] = pkh(r1[2 * gc + 16], r1[2 * gc + 17]);
        }
    }

    __syncthreads();

    const uint32_t cL = (uint32_t)(lane * 16);

    const int p0b = (lane >> 2) & 1;   // gr bit0 (xor 4)
    const int p1b = (lane >> 3) & 1;   // gr bit1 (xor 8)
    const int q0b = lane & 1;          // gc bit0 (xor 1)
    const int q1b = (lane >> 1) & 1;   // gc bit1 (xor 2)

    // Pooling for one (qi, B-frag set); returns part packed in both f16 halves
    auto pool_pair = [&](const ull* bf, const uint32_t* bh, int qi) -> uint32_t {
        uint32_t acc[2][4][2];
        #pragma unroll
        for (int mi = 0; mi < 2; ++mi)
            #pragma unroll
            for (int ni = 0; ni < 4; ++ni)
                hmma_z(acc[mi][ni], afr0[qi][mi], bf[ni]);
        #pragma unroll
        for (int mi = 0; mi < 2; ++mi)
            #pragma unroll
            for (int ni = 0; ni < 4; ++ni)
                hmma_k8(acc[mi][ni], afr1[qi][mi][0], afr1[qi][mi][1], bh[ni]);

        // In-thread packed row maxes over ni (4 slots)
        uint32_t rm[4];
        #pragma unroll
        for (int mi = 0; mi < 2; ++mi)
            #pragma unroll
            for (int j = 0; j < 2; ++j) {
                uint32_t m = hmax2u(acc[mi][0][j], acc[mi][1][j]);
                m = hmax2u(m, acc[mi][2][j]);
                rm[2 * mi + j] = hmax2u(m, acc[mi][3][j]);
            }
        // In-thread packed col maxes over rows (4 slots)
        uint32_t cm[4];
        #pragma unroll
        for (int ni = 0; ni < 4; ++ni) {
            uint32_t m = hmax2u(acc[0][ni][0], acc[0][ni][1]);
            m = hmax2u(m, acc[1][ni][0]);
            cm[ni] = hmax2u(m, acc[1][ni][1]);
        }

        // Rows: reduce-scatter over gc bits (xor 1, 2)
        uint32_t ro;
        {
            uint32_t s0 = q0b ? rm[0] : rm[2], k0v = q0b ? rm[2] : rm[0];
            uint32_t s1 = q0b ? rm[1] : rm[3], k1v = q0b ? rm[3] : rm[1];
            uint32_t w0 = hmax2u(k0v, __shfl_xor_sync(0xffffffffu, s0, 1));
            uint32_t w1 = hmax2u(k1v, __shfl_xor_sync(0xffffffffu, s1, 1));
            uint32_t s2 = q1b ? w0 : w1, k2v = q1b ? w1 : w0;
            ro = hmax2u(k2v, __shfl_xor_sync(0xffffffffu, s2, 2));
        }
        // Cols: reduce-scatter over gr bits (xor 4, 8) + butterfly (16)
        uint32_t cp;
        {
            uint32_t v4[2];
            #pragma unroll
            for (int j = 0; j < 2; ++j) {
                uint32_t s = p0b ? cm[j] : cm[j + 2];
                uint32_t k = p0b ? cm[j + 2] : cm[j];
                v4[j] = hmax2u(k, __shfl_xor_sync(0xffffffffu, s, 4));
            }
            uint32_t s = p1b ? v4[0] : v4[1];
            uint32_t k = p1b ? v4[1] : v4[0];
            uint32_t v2 = hmax2u(k, __shfl_xor_sync(0xffffffffu, s, 8));
            cp = hmax2u(v2, __shfl_xor_sync(0xffffffffu, v2, 16));
        }
        uint32_t rowm = hmax2u(ro, prmtu(ro, ro, 0x1032u));
        uint32_t csum = hadd2u(cp, prmtu(cp, cp, 0x1032u));
        return hfma2u(csum, 0x38003800u, rowm);   // part = rowm + 0.5*csum
    };

    #pragma unroll 1
    for (int kb = 0; kb < KCHUNK; kb += 8) {
        uint32_t pp[2][4], pfprev[2];

        #pragma unroll 1
        for (int kj = 0; kj < 8; ++kj) {
            const int kk = kb + kj;
            const char* b0 = sbuf + kk * 1024;
            ulonglong2 Av = *reinterpret_cast<const ulonglong2*>(b0 + cL);
            ulonglong2 Bv = *reinterpret_cast<const ulonglong2*>(b0 + 512 + cL);
            uint4 H = *reinterpret_cast<const uint4*>(sbuf + SB1_OFF + kk * 512 + cL);
            ull bf[4] = { Av.x, Av.y, Bv.x, Bv.y };
            uint32_t bh[4] = { H.x, H.y, H.z, H.w };

            #pragma unroll
            for (int qi = 0; qi < 2; ++qi) {
                uint32_t pf = pool_pair(bf, bh, qi);
                if (kj & 1) pp[qi][kj >> 1] = prmtu(pfprev[qi], pf, 0x5410u);
                else        pfprev[qi] = pf;
            }
        }

        // Two batched packed tails (one per q row)
        #pragma unroll
        for (int qi = 0; qi < 2; ++qi) {
            uint32_t t2[2];
            {
                bool hi = (lane & 1);
                #pragma unroll
                for (int j = 0; j < 2; ++j) {
                    uint32_t send = hi ? pp[qi][j] : pp[qi][j + 2];
                    uint32_t keep = hi ? pp[qi][j + 2] : pp[qi][j];
                    t2[j] = hadd2u(keep, __shfl_xor_sync(0xffffffffu, send, 1));
                }
            }
            uint32_t v;
            {
                bool hi = (lane & 2);
                uint32_t send = hi ? t2[0] : t2[1];
                uint32_t keep = hi ? t2[1] : t2[0];
                v = hadd2u(keep, __shfl_xor_sync(0xffffffffu, send, 2));
            }
            v = hadd2u(v, __shfl_xor_sync(0xffffffffu, v, 4));
            v = hadd2u(v, __shfl_xor_sync(0xffffffffu, v, 8));
            v = hadd2u(v, __shfl_xor_sync(0xffffffffu, v, 16));

            if (lane < 4) {
                int g = ((lane & 1) << 1) | ((lane >> 1) & 1);   // owned pp index
                float2 f = h2f2(v);
                float ra = 1.0f / (1.0f + __expf(f.x * -0.015625f));
                float rb = 1.0f / (1.0f + __expf(f.y * -0.015625f));
                int k = k0 + kb + 2 * g;
                float* o0 = out + (size_t)(q0 + 2 * warp + qi) * NK;
                float* o1 = o0 + (size_t)NQ * NK;
                *reinterpret_cast<float2*>(o0 + k) = make_float2(ra, rb);
                *reinterpret_cast<float2*>(o1 + k) = make_float2(ra, rb);
            }
        }
    }
}

extern "C" void kernel_launch(void* const* d_in, const int* in_sizes, int n_in,
                              void* d_out, int out_size)
{
    const float* tgt = (const float*)d_in[0];   // [128, 768]
    const float* mem = (const float*)d_in[1];   // [2048, 768]
    float* out = (float*)d_out;                 // [2, 128, 2048]
    (void)in_sizes; (void)n_in; (void)out_size;

    cudaFuncSetAttribute(matcher_hmma,
                         cudaFuncAttributeMaxDynamicSharedMemorySize, SMEM_BYTES);
    matcher_hmma<<<1024, NTHR, SMEM_BYTES>>>(tgt, mem, out);
}